// round 13
// baseline (speedup 1.0000x reference)
#include <cuda_runtime.h>
#include <cuda_bf16.h>
#include <cstdint>

#define CB_K    512
#define EMB_D   64
#define N_ROWS  65536
#define M_TILE  128
#define GRID    (N_ROWS / M_TILE)        // 512 CTAs
#define THREADS 128                      // 4 warps x 32 rows
#define Q_ELEMS ((size_t)N_ROWS * EMB_D)

#define SPLIT_SZ 65536                   // one bf16 split array: 512x32 words x4B
#define SM_SC   (3 * SPLIT_SZ)           // |e|^2 f32[512]
#define SM_AS   (SM_SC + 2048)           // A per row f32[128]
#define SM_BK   (SM_AS + 512)            // best idx int[128]
#define SM_RED  (SM_BK + 512)            // loss partials f32[128]
#define SM_TOTAL (SM_RED + 512)

__device__ float g_partial[GRID];

__device__ __forceinline__ void mma16816(float* c, const uint32_t* a,
                                         uint32_t b0, uint32_t b1) {
    asm volatile("mma.sync.aligned.m16n8k16.row.col.f32.bf16.bf16.f32 "
                 "{%0,%1,%2,%3}, {%4,%5,%6,%7}, {%8,%9}, {%0,%1,%2,%3};"
                 : "+f"(c[0]), "+f"(c[1]), "+f"(c[2]), "+f"(c[3])
                 : "r"(a[0]), "r"(a[1]), "r"(a[2]), "r"(a[3]), "r"(b0), "r"(b1));
}
__device__ __forceinline__ void split3(float v, __nv_bfloat16& s1,
                                       __nv_bfloat16& s2, __nv_bfloat16& s3) {
    s1 = __float2bfloat16_rn(v);
    float r = v - __bfloat162float(s1);
    s2 = __float2bfloat16_rn(r);
    s3 = __float2bfloat16_rn(r - __bfloat162float(s2));
}
__device__ __forceinline__ uint32_t packbf2(__nv_bfloat16 lo, __nv_bfloat16 hi) {
    return (uint32_t)__bfloat16_as_ushort(lo) | ((uint32_t)__bfloat16_as_ushort(hi) << 16);
}
// proven packed f32x2 helpers (A tree)
__device__ __forceinline__ unsigned long long fma2(unsigned long long a,
                                                   unsigned long long b,
                                                   unsigned long long c) {
    unsigned long long r;
    asm("fma.rn.f32x2 %0, %1, %2, %3;" : "=l"(r) : "l"(a), "l"(b), "l"(c));
    return r;
}
__device__ __forceinline__ unsigned long long add2(unsigned long long a,
                                                   unsigned long long b) {
    unsigned long long r;
    asm("add.rn.f32x2 %0, %1, %2;" : "=l"(r) : "l"(a), "l"(b));
    return r;
}
__device__ __forceinline__ unsigned long long pk2(float lo, float hi) {
    unsigned long long r;
    asm("mov.b64 %0, {%1, %2};" : "=l"(r) : "f"(lo), "f"(hi));
    return r;
}
__device__ __forceinline__ float lo2(unsigned long long v) {
    return __uint_as_float((unsigned)(v & 0xffffffffull));
}
__device__ __forceinline__ float hi2(unsigned long long v) {
    return __uint_as_float((unsigned)(v >> 32));
}

__global__ void __launch_bounds__(THREADS)
vq_mma_kernel(const float* __restrict__ x_g,
              const float* __restrict__ e_g,
              float* __restrict__ out) {
    extern __shared__ char smem[];
    const int tid  = threadIdx.x;
    const int lane = tid & 31;
    const int wid  = tid >> 5;
    const int g    = lane >> 2;          // 0..7
    const int tq   = lane & 3;           // 0..3

    // ---- stage e as 3 bf16 split arrays, swizzled word w -> w ^ ((code&7)<<2) ----
    for (int i = tid; i < CB_K * 32; i += THREADS) {
        float2 v = reinterpret_cast<const float2*>(e_g)[i];   // code i>>5, dims 2w,2w+1
        __nv_bfloat16 a1, a2, a3, b1, b2, b3;
        split3(v.x, a1, a2, a3);
        split3(v.y, b1, b2, b3);
        int code = i >> 5, w = i & 31;
        uint32_t soff = (uint32_t)(code * 128 + ((w ^ ((code & 7) << 2)) << 2));
        *reinterpret_cast<uint32_t*>(smem + 0 * SPLIT_SZ + soff) = packbf2(a1, b1);
        *reinterpret_cast<uint32_t*>(smem + 1 * SPLIT_SZ + soff) = packbf2(a2, b2);
        *reinterpret_cast<uint32_t*>(smem + 2 * SPLIT_SZ + soff) = packbf2(a3, b3);
    }
    // ---- |e_k|^2 (proven serial chain) ----
    {
        float* sc = reinterpret_cast<float*>(smem + SM_SC);
        for (int k = tid; k < CB_K; k += THREADS) {
            const float* er = e_g + (size_t)k * EMB_D;
            float s = 0.f;
            #pragma unroll 16
            for (int d = 0; d < EMB_D; d++) s = __fmaf_rn(er[d], er[d], s);
            sc[k] = s;
        }
    }
    // ---- A = |x|^2 for own row (proven fma2 tree, same bits as R8) ----
    const int ctabase = blockIdx.x * M_TILE;
    {
        const float4* xr = reinterpret_cast<const float4*>(x_g + (size_t)(ctabase + tid) * EMB_D);
        unsigned long long xx0[8];
        unsigned long long a0 = 0, a1 = 0, a2 = 0, a3 = 0;
        #pragma unroll
        for (int blk = 0; blk < 4; blk++) {
            #pragma unroll
            for (int i = 0; i < 4; i++) {
                float4 f = xr[blk * 4 + i];
                xx0[2 * i]     = pk2(f.x, f.y);
                xx0[2 * i + 1] = pk2(f.z, f.w);
            }
            a0 = fma2(xx0[0], xx0[0], a0); a1 = fma2(xx0[1], xx0[1], a1);
            a2 = fma2(xx0[2], xx0[2], a2); a3 = fma2(xx0[3], xx0[3], a3);
            a0 = fma2(xx0[4], xx0[4], a0); a1 = fma2(xx0[5], xx0[5], a1);
            a2 = fma2(xx0[6], xx0[6], a2); a3 = fma2(xx0[7], xx0[7], a3);
        }
        unsigned long long s = add2(add2(a0, a2), add2(a1, a3));
        reinterpret_cast<float*>(smem + SM_AS)[tid] = lo2(s) + hi2(s);
    }
    // ---- load A-fragments (3 splits x 2 mtiles x 4 ktiles x 4 regs) ----
    uint32_t areg[3][2][4][4];
    {
        const int wrow = ctabase + wid * 32;
        #pragma unroll
        for (int mt = 0; mt < 2; mt++)
            #pragma unroll
            for (int kt = 0; kt < 4; kt++)
                #pragma unroll
                for (int p = 0; p < 4; p++) {
                    int row = wrow + mt * 16 + g + (p & 1) * 8;
                    int col = kt * 16 + 2 * tq + (p >> 1) * 8;
                    float2 v = *reinterpret_cast<const float2*>(x_g + (size_t)row * EMB_D + col);
                    __nv_bfloat16 u1, u2, u3, w1, w2, w3;
                    split3(v.x, u1, u2, u3);
                    split3(v.y, w1, w2, w3);
                    areg[0][mt][kt][p] = packbf2(u1, w1);
                    areg[1][mt][kt][p] = packbf2(u2, w2);
                    areg[2][mt][kt][p] = packbf2(u3, w3);
                }
    }
    __syncthreads();

    // A for my 4 result rows (rows g, g+8 of each mtile)
    const float* As = reinterpret_cast<const float*>(smem + SM_AS);
    float Arow[2][2];
    #pragma unroll
    for (int mt = 0; mt < 2; mt++) {
        Arow[mt][0] = As[wid * 32 + mt * 16 + g];
        Arow[mt][1] = As[wid * 32 + mt * 16 + g + 8];
    }

    const float* scp = reinterpret_cast<const float*>(smem + SM_SC);
    const uint32_t swz = (uint32_t)(g << 2);
    float best[2][2] = {{3.4e38f, 3.4e38f}, {3.4e38f, 3.4e38f}};
    int   bidx[2][2] = {{0, 0}, {0, 0}};

    #pragma unroll 1
    for (int nt = 0; nt < 64; nt++) {
        const uint32_t rowoff = (uint32_t)((nt * 8 + g) * 128);
        float cb[2][4] = {{0.f,0.f,0.f,0.f},{0.f,0.f,0.f,0.f}};   // x1e1
        float cs[2][4] = {{0.f,0.f,0.f,0.f},{0.f,0.f,0.f,0.f}};   // low-order sum
        #pragma unroll
        for (int kt = 0; kt < 4; kt++) {
            uint32_t w0 = (uint32_t)(kt * 8 + tq);
            uint32_t o0 = rowoff + (((w0    ) ^ swz) << 2);
            uint32_t o1 = rowoff + (((w0 + 4) ^ swz) << 2);
            uint32_t e10 = *reinterpret_cast<const uint32_t*>(smem + 0 * SPLIT_SZ + o0);
            uint32_t e11 = *reinterpret_cast<const uint32_t*>(smem + 0 * SPLIT_SZ + o1);
            uint32_t e20 = *reinterpret_cast<const uint32_t*>(smem + 1 * SPLIT_SZ + o0);
            uint32_t e21 = *reinterpret_cast<const uint32_t*>(smem + 1 * SPLIT_SZ + o1);
            uint32_t e30 = *reinterpret_cast<const uint32_t*>(smem + 2 * SPLIT_SZ + o0);
            uint32_t e31 = *reinterpret_cast<const uint32_t*>(smem + 2 * SPLIT_SZ + o1);
            #pragma unroll
            for (int mt = 0; mt < 2; mt++) {
                mma16816(cb[mt], areg[0][mt][kt], e10, e11);   // x1 e1 (big)
                mma16816(cs[mt], areg[1][mt][kt], e10, e11);   // x2 e1
                mma16816(cs[mt], areg[0][mt][kt], e20, e21);   // x1 e2
                mma16816(cs[mt], areg[1][mt][kt], e20, e21);   // x2 e2
                mma16816(cs[mt], areg[2][mt][kt], e10, e11);   // x3 e1
                mma16816(cs[mt], areg[0][mt][kt], e30, e31);   // x1 e3
            }
        }
        // tail: dd = fl(fl(A - 2B) + C), ascending code, strict <
        const int c0 = nt * 8 + 2 * tq;
        const float ck0 = scp[c0], ck1 = scp[c0 + 1];
        #pragma unroll
        for (int mt = 0; mt < 2; mt++)
            #pragma unroll
            for (int rh = 0; rh < 2; rh++) {
                float B0 = __fadd_rn(cb[mt][2 * rh],     cs[mt][2 * rh]);
                float B1 = __fadd_rn(cb[mt][2 * rh + 1], cs[mt][2 * rh + 1]);
                float dd0 = __fadd_rn(__fmaf_rn(-2.0f, B0, Arow[mt][rh]), ck0);
                float dd1 = __fadd_rn(__fmaf_rn(-2.0f, B1, Arow[mt][rh]), ck1);
                if (dd0 < best[mt][rh]) { best[mt][rh] = dd0; bidx[mt][rh] = c0; }
                if (dd1 < best[mt][rh]) { best[mt][rh] = dd1; bidx[mt][rh] = c0 + 1; }
            }
    }
    // ---- merge across the 4 tq lanes of each row (min, lowest index on tie) ----
    int* bkArr = reinterpret_cast<int*>(smem + SM_BK);
    #pragma unroll
    for (int mt = 0; mt < 2; mt++)
        #pragma unroll
        for (int rh = 0; rh < 2; rh++) {
            float b = best[mt][rh];
            int   i = bidx[mt][rh];
            #pragma unroll
            for (int m = 1; m <= 2; m <<= 1) {
                float ob = __shfl_xor_sync(0xffffffffu, b, m);
                int   oi = __shfl_xor_sync(0xffffffffu, i, m);
                if (ob < b || (ob == b && oi < i)) { b = ob; i = oi; }
            }
            if (tq == 0) bkArr[wid * 32 + mt * 16 + rh * 8 + g] = i;
        }
    __syncthreads();

    // ---- epilogue: one thread per row ----
    const int row = ctabase + tid;
    const int bk  = bkArr[tid];
    float sse = 0.f;
    {
        const float4* qe = reinterpret_cast<const float4*>(e_g + (size_t)bk * EMB_D);
        const float4* xr = reinterpret_cast<const float4*>(x_g + (size_t)row * EMB_D);
        float q[64];
        #pragma unroll
        for (int i = 0; i < 16; i++) {
            float4 qq = qe[i];
            float4 xx = xr[i];
            q[4*i] = qq.x; q[4*i+1] = qq.y; q[4*i+2] = qq.z; q[4*i+3] = qq.w;
            float d0 = qq.x - xx.x, d1 = qq.y - xx.y;
            float d2 = qq.z - xx.z, d3 = qq.w - xx.w;
            sse = __fmaf_rn(d0, d0, sse);
            sse = __fmaf_rn(d1, d1, sse);
            sse = __fmaf_rn(d2, d2, sse);
            sse = __fmaf_rn(d3, d3, sse);
        }
        float* orow = out + 1 + (size_t)row * EMB_D;
        orow[0] = q[0]; orow[1] = q[1]; orow[2] = q[2];
        float4* ov = reinterpret_cast<float4*>(orow + 3);   // 16B aligned (4+64r)
        #pragma unroll
        for (int i = 0; i < 15; i++) {
            float4 v;
            v.x = q[3+4*i]; v.y = q[4+4*i]; v.z = q[5+4*i]; v.w = q[6+4*i];
            ov[i] = v;
        }
        orow[63] = q[63];
    }
    out[1 + Q_ELEMS + (size_t)row] = (float)bk;

    // ---- CTA loss reduction (deterministic tree) ----
    float* sred = reinterpret_cast<float*>(smem + SM_RED);
    sred[tid] = sse;
    __syncthreads();
    #pragma unroll
    for (int off = THREADS / 2; off > 0; off >>= 1) {
        if (tid < off) sred[tid] = sred[tid] + sred[tid + off];
        __syncthreads();
    }
    if (tid == 0) g_partial[blockIdx.x] = sred[0];
}

// Final deterministic reduce: loss = 1.25 * SSE / (N*D)
__global__ void vq_reduce_kernel(float* __restrict__ out) {
    __shared__ double sd[GRID];
    int tid = threadIdx.x;
    sd[tid] = (double)g_partial[tid];
    __syncthreads();
    #pragma unroll
    for (int off = GRID / 2; off > 0; off >>= 1) {
        if (tid < off) sd[tid] = sd[tid] + sd[tid + off];
        __syncthreads();
    }
    if (tid == 0) {
        double mean = sd[0] / (double)((size_t)N_ROWS * EMB_D);
        out[0] = (float)(1.25 * mean);
    }
}

extern "C" void kernel_launch(void* const* d_in, const int* in_sizes, int n_in,
                              void* d_out, int out_size) {
    const float* x = (const float*)d_in[0];
    const float* e = (const float*)d_in[1];
    if (n_in >= 2 && in_sizes[0] == CB_K * EMB_D) {
        const float* t = x; x = e; e = t;
    }
    float* out = (float*)d_out;

    cudaFuncSetAttribute(vq_mma_kernel,
                         cudaFuncAttributeMaxDynamicSharedMemorySize, SM_TOTAL);
    vq_mma_kernel<<<GRID, THREADS, SM_TOTAL>>>(x, e, out);
    vq_reduce_kernel<<<1, GRID>>>(out);
}

// round 15
// speedup vs baseline: 1.1606x; 1.1606x over previous
#include <cuda_runtime.h>
#include <cuda_bf16.h>
#include <cstdint>

#define CB_K    512
#define EMB_D   64
#define N_ROWS  65536
#define M_TILE  128
#define GRID    (N_ROWS / M_TILE)        // 512 CTAs
#define THREADS 256                      // 8 warps x 16 rows
#define Q_ELEMS ((size_t)N_ROWS * EMB_D)

#define SPLIT_SZ 65536                   // one bf16 split array: 512 codes x 32 words x 4B
#define SM_SC   (3 * SPLIT_SZ)           // 196608: |e|^2 f32[512]
#define SM_AS   (SM_SC + 2048)           // A per row f32[128]
#define SM_BK   (SM_AS + 512)            // best idx int[128]
#define SM_RED  (SM_BK + 512)            // loss partials f32[256]
#define SM_TOTAL (SM_RED + 1024)         // 200704 bytes

__device__ float g_partial[GRID];

__device__ __forceinline__ void mma16816(float* c, const uint32_t* a,
                                         uint32_t b0, uint32_t b1) {
    asm volatile("mma.sync.aligned.m16n8k16.row.col.f32.bf16.bf16.f32 "
                 "{%0,%1,%2,%3}, {%4,%5,%6,%7}, {%8,%9}, {%0,%1,%2,%3};"
                 : "+f"(c[0]), "+f"(c[1]), "+f"(c[2]), "+f"(c[3])
                 : "r"(a[0]), "r"(a[1]), "r"(a[2]), "r"(a[3]), "r"(b0), "r"(b1));
}
__device__ __forceinline__ void split3(float v, __nv_bfloat16& s1,
                                       __nv_bfloat16& s2, __nv_bfloat16& s3) {
    s1 = __float2bfloat16_rn(v);
    float r = v - __bfloat162float(s1);
    s2 = __float2bfloat16_rn(r);
    s3 = __float2bfloat16_rn(r - __bfloat162float(s2));
}
__device__ __forceinline__ uint32_t packbf2(__nv_bfloat16 lo, __nv_bfloat16 hi) {
    return (uint32_t)__bfloat16_as_ushort(lo) | ((uint32_t)__bfloat16_as_ushort(hi) << 16);
}
// proven packed f32x2 helpers (A tree)
__device__ __forceinline__ unsigned long long fma2(unsigned long long a,
                                                   unsigned long long b,
                                                   unsigned long long c) {
    unsigned long long r;
    asm("fma.rn.f32x2 %0, %1, %2, %3;" : "=l"(r) : "l"(a), "l"(b), "l"(c));
    return r;
}
__device__ __forceinline__ unsigned long long add2(unsigned long long a,
                                                   unsigned long long b) {
    unsigned long long r;
    asm("add.rn.f32x2 %0, %1, %2;" : "=l"(r) : "l"(a), "l"(b));
    return r;
}
__device__ __forceinline__ unsigned long long pk2(float lo, float hi) {
    unsigned long long r;
    asm("mov.b64 %0, {%1, %2};" : "=l"(r) : "f"(lo), "f"(hi));
    return r;
}
__device__ __forceinline__ float lo2(unsigned long long v) {
    return __uint_as_float((unsigned)(v & 0xffffffffull));
}
__device__ __forceinline__ float hi2(unsigned long long v) {
    return __uint_as_float((unsigned)(v >> 32));
}

__global__ void __launch_bounds__(THREADS)
vq_mma_kernel(const float* __restrict__ x_g,
              const float* __restrict__ e_g,
              float* __restrict__ out) {
    extern __shared__ char smem[];
    const int tid  = threadIdx.x;
    const int lane = tid & 31;
    const int wid  = tid >> 5;           // 0..7, warp owns rows [wid*16, wid*16+16)
    const int g    = lane >> 2;          // 0..7
    const int tq   = lane & 3;           // 0..3

    // ---- stage e as 3 bf16 split arrays, swizzled word w -> w ^ ((code&7)<<2) ----
    #pragma unroll 4
    for (int t = 0; t < (CB_K * 32) / THREADS; t++) {
        int i = tid + t * THREADS;
        float2 v = reinterpret_cast<const float2*>(e_g)[i];   // code i>>5, dims 2w,2w+1
        __nv_bfloat16 a1, a2, a3, b1, b2, b3;
        split3(v.x, a1, a2, a3);
        split3(v.y, b1, b2, b3);
        int code = i >> 5, w = i & 31;
        uint32_t soff = (uint32_t)(code * 128 + ((w ^ ((code & 7) << 2)) << 2));
        *reinterpret_cast<uint32_t*>(smem + 0 * SPLIT_SZ + soff) = packbf2(a1, b1);
        *reinterpret_cast<uint32_t*>(smem + 1 * SPLIT_SZ + soff) = packbf2(a2, b2);
        *reinterpret_cast<uint32_t*>(smem + 2 * SPLIT_SZ + soff) = packbf2(a3, b3);
    }
    // ---- |e_k|^2 (proven serial chain) ----
    {
        float* sc = reinterpret_cast<float*>(smem + SM_SC);
        #pragma unroll
        for (int kk = 0; kk < CB_K / THREADS; kk++) {
            int k = tid + kk * THREADS;
            const float* er = e_g + (size_t)k * EMB_D;
            float s = 0.f;
            #pragma unroll 16
            for (int d = 0; d < EMB_D; d++) s = __fmaf_rn(er[d], er[d], s);
            sc[k] = s;
        }
    }
    // ---- A = |x|^2 for rows (tid<128), proven fma2 tree -> same bits as R8 ----
    const int ctabase = blockIdx.x * M_TILE;
    if (tid < M_TILE) {
        const float4* xr = reinterpret_cast<const float4*>(x_g + (size_t)(ctabase + tid) * EMB_D);
        unsigned long long xx0[8];
        unsigned long long a0 = 0, a1 = 0, a2 = 0, a3 = 0;
        #pragma unroll
        for (int blk = 0; blk < 4; blk++) {
            #pragma unroll
            for (int i = 0; i < 4; i++) {
                float4 f = xr[blk * 4 + i];
                xx0[2 * i]     = pk2(f.x, f.y);
                xx0[2 * i + 1] = pk2(f.z, f.w);
            }
            a0 = fma2(xx0[0], xx0[0], a0); a1 = fma2(xx0[1], xx0[1], a1);
            a2 = fma2(xx0[2], xx0[2], a2); a3 = fma2(xx0[3], xx0[3], a3);
            a0 = fma2(xx0[4], xx0[4], a0); a1 = fma2(xx0[5], xx0[5], a1);
            a2 = fma2(xx0[6], xx0[6], a2); a3 = fma2(xx0[7], xx0[7], a3);
        }
        unsigned long long s = add2(add2(a0, a2), add2(a1, a3));
        reinterpret_cast<float*>(smem + SM_AS)[tid] = lo2(s) + hi2(s);
    }
    // ---- load A-fragments: 3 splits x 4 ktiles x 4 regs (one 16-row mtile/warp) ----
    uint32_t areg[3][4][4];
    {
        const int wrow = ctabase + wid * 16;
        #pragma unroll
        for (int kt = 0; kt < 4; kt++)
            #pragma unroll
            for (int p = 0; p < 4; p++) {
                int row = wrow + g + (p & 1) * 8;
                int col = kt * 16 + 2 * tq + (p >> 1) * 8;
                float2 v = *reinterpret_cast<const float2*>(x_g + (size_t)row * EMB_D + col);
                __nv_bfloat16 u1, u2, u3, w1, w2, w3;
                split3(v.x, u1, u2, u3);
                split3(v.y, w1, w2, w3);
                areg[0][kt][p] = packbf2(u1, w1);
                areg[1][kt][p] = packbf2(u2, w2);
                areg[2][kt][p] = packbf2(u3, w3);
            }
    }
    __syncthreads();

    // A for my 2 result rows (g, g+8 of the warp's mtile)
    const float* As = reinterpret_cast<const float*>(smem + SM_AS);
    float Arow0 = As[wid * 16 + g];
    float Arow1 = As[wid * 16 + g + 8];

    const float* scp = reinterpret_cast<const float*>(smem + SM_SC);
    const uint32_t swz = (uint32_t)(g << 2);
    // per-half bests: U = tiles [0,32) codes <256, V = tiles [32,64) codes >=256
    float bU0 = 3.4e38f, bU1 = 3.4e38f, bV0 = 3.4e38f, bV1 = 3.4e38f;
    int   iU0 = 0, iU1 = 0, iV0 = 256, iV1 = 256;

    #pragma unroll 1
    for (int nt = 0; nt < 32; nt++) {
        const uint32_t roffU = (uint32_t)((nt * 8 + g) * 128);
        const uint32_t roffV = (uint32_t)(((nt + 32) * 8 + g) * 128);
        // 4 independent accumulator chains: (cbU,csU) and (cbV,csV)
        float cbU[4] = {0.f,0.f,0.f,0.f}, csU[4] = {0.f,0.f,0.f,0.f};
        float cbV[4] = {0.f,0.f,0.f,0.f}, csV[4] = {0.f,0.f,0.f,0.f};
        #pragma unroll
        for (int kt = 0; kt < 4; kt++) {
            uint32_t w0 = (uint32_t)(kt * 8 + tq);
            uint32_t d0 = (((w0    ) ^ swz) << 2);
            uint32_t d1 = (((w0 + 4) ^ swz) << 2);
            uint32_t u10 = *reinterpret_cast<const uint32_t*>(smem + 0*SPLIT_SZ + roffU + d0);
            uint32_t u11 = *reinterpret_cast<const uint32_t*>(smem + 0*SPLIT_SZ + roffU + d1);
            uint32_t u20 = *reinterpret_cast<const uint32_t*>(smem + 1*SPLIT_SZ + roffU + d0);
            uint32_t u21 = *reinterpret_cast<const uint32_t*>(smem + 1*SPLIT_SZ + roffU + d1);
            uint32_t u30 = *reinterpret_cast<const uint32_t*>(smem + 2*SPLIT_SZ + roffU + d0);
            uint32_t u31 = *reinterpret_cast<const uint32_t*>(smem + 2*SPLIT_SZ + roffU + d1);
            uint32_t v10 = *reinterpret_cast<const uint32_t*>(smem + 0*SPLIT_SZ + roffV + d0);
            uint32_t v11 = *reinterpret_cast<const uint32_t*>(smem + 0*SPLIT_SZ + roffV + d1);
            uint32_t v20 = *reinterpret_cast<const uint32_t*>(smem + 1*SPLIT_SZ + roffV + d0);
            uint32_t v21 = *reinterpret_cast<const uint32_t*>(smem + 1*SPLIT_SZ + roffV + d1);
            uint32_t v30 = *reinterpret_cast<const uint32_t*>(smem + 2*SPLIT_SZ + roffV + d0);
            uint32_t v31 = *reinterpret_cast<const uint32_t*>(smem + 2*SPLIT_SZ + roffV + d1);
            // R13 order per tile: cb:x1e1 ; cs: x2e1, x1e2, x2e2, x3e1, x1e3
            mma16816(cbU, areg[0][kt], u10, u11);
            mma16816(cbV, areg[0][kt], v10, v11);
            mma16816(csU, areg[1][kt], u10, u11);
            mma16816(csV, areg[1][kt], v10, v11);
            mma16816(csU, areg[0][kt], u20, u21);
            mma16816(csV, areg[0][kt], v20, v21);
            mma16816(csU, areg[1][kt], u20, u21);
            mma16816(csV, areg[1][kt], v20, v21);
            mma16816(csU, areg[2][kt], u10, u11);
            mma16816(csV, areg[2][kt], v10, v11);
            mma16816(csU, areg[0][kt], u30, u31);
            mma16816(csV, areg[0][kt], v30, v31);
        }
        // tails (proven association), ascending code within each half, strict <
        {
            const int c0 = nt * 8 + 2 * tq;
            const float ck0 = scp[c0], ck1 = scp[c0 + 1];
            float B00 = __fadd_rn(cbU[0], csU[0]);
            float B01 = __fadd_rn(cbU[1], csU[1]);
            float B10 = __fadd_rn(cbU[2], csU[2]);
            float B11 = __fadd_rn(cbU[3], csU[3]);
            float d00 = __fadd_rn(__fmaf_rn(-2.0f, B00, Arow0), ck0);
            float d01 = __fadd_rn(__fmaf_rn(-2.0f, B01, Arow0), ck1);
            float d10 = __fadd_rn(__fmaf_rn(-2.0f, B10, Arow1), ck0);
            float d11 = __fadd_rn(__fmaf_rn(-2.0f, B11, Arow1), ck1);
            if (d00 < bU0) { bU0 = d00; iU0 = c0; }
            if (d01 < bU0) { bU0 = d01; iU0 = c0 + 1; }
            if (d10 < bU1) { bU1 = d10; iU1 = c0; }
            if (d11 < bU1) { bU1 = d11; iU1 = c0 + 1; }
        }
        {
            const int c0 = (nt + 32) * 8 + 2 * tq;
            const float ck0 = scp[c0], ck1 = scp[c0 + 1];
            float B00 = __fadd_rn(cbV[0], csV[0]);
            float B01 = __fadd_rn(cbV[1], csV[1]);
            float B10 = __fadd_rn(cbV[2], csV[2]);
            float B11 = __fadd_rn(cbV[3], csV[3]);
            float d00 = __fadd_rn(__fmaf_rn(-2.0f, B00, Arow0), ck0);
            float d01 = __fadd_rn(__fmaf_rn(-2.0f, B01, Arow0), ck1);
            float d10 = __fadd_rn(__fmaf_rn(-2.0f, B10, Arow1), ck0);
            float d11 = __fadd_rn(__fmaf_rn(-2.0f, B11, Arow1), ck1);
            if (d00 < bV0) { bV0 = d00; iV0 = c0; }
            if (d01 < bV0) { bV0 = d01; iV0 = c0 + 1; }
            if (d10 < bV1) { bV1 = d10; iV1 = c0; }
            if (d11 < bV1) { bV1 = d11; iV1 = c0 + 1; }
        }
    }
    // merge halves (V codes all higher: strict < keeps lower half on ties)
    float best0 = bU0; int bidx0 = iU0;
    if (bV0 < best0) { best0 = bV0; bidx0 = iV0; }
    float best1 = bU1; int bidx1 = iU1;
    if (bV1 < best1) { best1 = bV1; bidx1 = iV1; }

    // ---- merge across the 4 tq lanes of each row (min, lowest index on tie) ----
    int* bkArr = reinterpret_cast<int*>(smem + SM_BK);
    {
        float b = best0; int i = bidx0;
        #pragma unroll
        for (int m = 1; m <= 2; m <<= 1) {
            float ob = __shfl_xor_sync(0xffffffffu, b, m);
            int   oi = __shfl_xor_sync(0xffffffffu, i, m);
            if (ob < b || (ob == b && oi < i)) { b = ob; i = oi; }
        }
        if (tq == 0) bkArr[wid * 16 + g] = i;
    }
    {
        float b = best1; int i = bidx1;
        #pragma unroll
        for (int m = 1; m <= 2; m <<= 1) {
            float ob = __shfl_xor_sync(0xffffffffu, b, m);
            int   oi = __shfl_xor_sync(0xffffffffu, i, m);
            if (ob < b || (ob == b && oi < i)) { b = ob; i = oi; }
        }
        if (tq == 0) bkArr[wid * 16 + g + 8] = i;
    }
    __syncthreads();

    // ---- epilogue: one thread per row (tid < 128) ----
    float sse = 0.f;
    if (tid < M_TILE) {
        const int row = ctabase + tid;
        const int bk  = bkArr[tid];
        const float4* qe = reinterpret_cast<const float4*>(e_g + (size_t)bk * EMB_D);
        const float4* xr = reinterpret_cast<const float4*>(x_g + (size_t)row * EMB_D);
        float q[64];
        #pragma unroll
        for (int i = 0; i < 16; i++) {
            float4 qq = qe[i];
            float4 xx = xr[i];
            q[4*i] = qq.x; q[4*i+1] = qq.y; q[4*i+2] = qq.z; q[4*i+3] = qq.w;
            float d0 = qq.x - xx.x, d1 = qq.y - xx.y;
            float d2 = qq.z - xx.z, d3 = qq.w - xx.w;
            sse = __fmaf_rn(d0, d0, sse);
            sse = __fmaf_rn(d1, d1, sse);
            sse = __fmaf_rn(d2, d2, sse);
            sse = __fmaf_rn(d3, d3, sse);
        }
        float* orow = out + 1 + (size_t)row * EMB_D;
        orow[0] = q[0]; orow[1] = q[1]; orow[2] = q[2];
        float4* ov = reinterpret_cast<float4*>(orow + 3);   // 16B aligned (4+64r)
        #pragma unroll
        for (int i = 0; i < 15; i++) {
            float4 v;
            v.x = q[3+4*i]; v.y = q[4+4*i]; v.z = q[5+4*i]; v.w = q[6+4*i];
            ov[i] = v;
        }
        orow[63] = q[63];
        out[1 + Q_ELEMS + (size_t)row] = (float)bk;
    }

    // ---- CTA loss reduction (deterministic tree over 256 threads) ----
    float* sred = reinterpret_cast<float*>(smem + SM_RED);
    sred[tid] = sse;
    __syncthreads();
    #pragma unroll
    for (int off = THREADS / 2; off > 0; off >>= 1) {
        if (tid < off) sred[tid] = sred[tid] + sred[tid + off];
        __syncthreads();
    }
    if (tid == 0) g_partial[blockIdx.x] = sred[0];
}

// Final deterministic reduce: loss = 1.25 * SSE / (N*D)
__global__ void vq_reduce_kernel(float* __restrict__ out) {
    __shared__ double sd[GRID];
    int tid = threadIdx.x;
    sd[tid] = (double)g_partial[tid];
    __syncthreads();
    #pragma unroll
    for (int off = GRID / 2; off > 0; off >>= 1) {
        if (tid < off) sd[tid] = sd[tid] + sd[tid + off];
        __syncthreads();
    }
    if (tid == 0) {
        double mean = sd[0] / (double)((size_t)N_ROWS * EMB_D);
        out[0] = (float)(1.25 * mean);
    }
}

extern "C" void kernel_launch(void* const* d_in, const int* in_sizes, int n_in,
                              void* d_out, int out_size) {
    const float* x = (const float*)d_in[0];
    const float* e = (const float*)d_in[1];
    if (n_in >= 2 && in_sizes[0] == CB_K * EMB_D) {
        const float* t = x; x = e; e = t;
    }
    float* out = (float*)d_out;

    cudaFuncSetAttribute(vq_mma_kernel,
                         cudaFuncAttributeMaxDynamicSharedMemorySize, SM_TOTAL);
    vq_mma_kernel<<<GRID, THREADS, SM_TOTAL>>>(x, e, out);
    vq_reduce_kernel<<<1, GRID>>>(out);
}

// round 16
// speedup vs baseline: 1.3268x; 1.1433x over previous
#include <cuda_runtime.h>
#include <cuda_bf16.h>
#include <cstdint>

#define CB_K    512
#define S_CODES 344                      // scalar half: codes [0,344)
#define T_CODES 168                      // tensor half: codes [344,512)
#define NT_T    21                       // 168/8 n-tiles
#define EMB_D   64
#define N_ROWS  65536
#define CTA_ROWS 256
#define GRID    (N_ROWS / CTA_ROWS)      // 256 CTAs
#define THREADS 256                      // warps 0-3 scalar, 4-7 tensor
#define Q_ELEMS ((size_t)N_ROWS * EMB_D)

#define SPL_STRIDE 21504                 // 168 codes x 128B per split
#define SM_E    0                        // fp32 codes[344][64] = 88064 B
#define SM_SPL  88064                    // 3 x 21504 = 64512 B
#define SM_SC   (SM_SPL + 3 * SPL_STRIDE)   // 152576: |e|^2 f32[512]
#define SM_AS   (SM_SC + 2048)           // 154624: A f32[256]
#define SM_BT   (SM_AS + 1024)           // 155648: tensor best f32[256]
#define SM_IT   (SM_BT + 1024)           // 156672: tensor idx i32[256]
#define SM_RED  (SM_IT + 1024)           // 157696: partials f32[256]
#define SM_TOTAL (SM_RED + 1024)         // 158720 B

__device__ float g_partial[GRID];

__device__ __forceinline__ void mma16816(float* c, const uint32_t* a,
                                         uint32_t b0, uint32_t b1) {
    asm volatile("mma.sync.aligned.m16n8k16.row.col.f32.bf16.bf16.f32 "
                 "{%0,%1,%2,%3}, {%4,%5,%6,%7}, {%8,%9}, {%0,%1,%2,%3};"
                 : "+f"(c[0]), "+f"(c[1]), "+f"(c[2]), "+f"(c[3])
                 : "r"(a[0]), "r"(a[1]), "r"(a[2]), "r"(a[3]), "r"(b0), "r"(b1));
}
__device__ __forceinline__ void split3(float v, __nv_bfloat16& s1,
                                       __nv_bfloat16& s2, __nv_bfloat16& s3) {
    s1 = __float2bfloat16_rn(v);
    float r = v - __bfloat162float(s1);
    s2 = __float2bfloat16_rn(r);
    s3 = __float2bfloat16_rn(r - __bfloat162float(s2));
}
__device__ __forceinline__ uint32_t packbf2(__nv_bfloat16 lo, __nv_bfloat16 hi) {
    return (uint32_t)__bfloat16_as_ushort(lo) | ((uint32_t)__bfloat16_as_ushort(hi) << 16);
}
// proven packed f32x2 helpers
__device__ __forceinline__ unsigned long long fma2(unsigned long long a,
                                                   unsigned long long b,
                                                   unsigned long long c) {
    unsigned long long r;
    asm("fma.rn.f32x2 %0, %1, %2, %3;" : "=l"(r) : "l"(a), "l"(b), "l"(c));
    return r;
}
__device__ __forceinline__ unsigned long long add2(unsigned long long a,
                                                   unsigned long long b) {
    unsigned long long r;
    asm("add.rn.f32x2 %0, %1, %2;" : "=l"(r) : "l"(a), "l"(b));
    return r;
}
__device__ __forceinline__ unsigned long long pk2(float lo, float hi) {
    unsigned long long r;
    asm("mov.b64 %0, {%1, %2};" : "=l"(r) : "f"(lo), "f"(hi));
    return r;
}
__device__ __forceinline__ float lo2(unsigned long long v) {
    return __uint_as_float((unsigned)(v & 0xffffffffull));
}
__device__ __forceinline__ float hi2(unsigned long long v) {
    return __uint_as_float((unsigned)(v >> 32));
}

__global__ void __launch_bounds__(THREADS, 1)
vq_hybrid_kernel(const float* __restrict__ x_g,
                 const float* __restrict__ e_g,
                 float* __restrict__ out) {
    extern __shared__ char smem[];
    const int tid  = threadIdx.x;
    const int lane = tid & 31;
    const int wid  = tid >> 5;
    const int ctabase = blockIdx.x * CTA_ROWS;

    // ================= staging (all 256 threads) =================
    // fp32 low-codebook [0,344): linear [code][64]
    {
        float4* dst = reinterpret_cast<float4*>(smem + SM_E);
        const float4* src = reinterpret_cast<const float4*>(e_g);
        for (int i = tid; i < S_CODES * 16; i += THREADS) dst[i] = src[i];
    }
    // bf16 3-split arrays for codes [344,512), swizzled word w -> w^((lc&7)<<2)
    for (int i = tid; i < T_CODES * 32; i += THREADS) {
        int lc = i >> 5, w = i & 31;
        float2 v = reinterpret_cast<const float2*>(e_g)[(size_t)(S_CODES + lc) * 32 + w];
        __nv_bfloat16 a1, a2, a3, b1, b2, b3;
        split3(v.x, a1, a2, a3);
        split3(v.y, b1, b2, b3);
        uint32_t soff = (uint32_t)(lc * 128 + ((w ^ ((lc & 7) << 2)) << 2));
        *reinterpret_cast<uint32_t*>(smem + SM_SPL + 0 * SPL_STRIDE + soff) = packbf2(a1, b1);
        *reinterpret_cast<uint32_t*>(smem + SM_SPL + 1 * SPL_STRIDE + soff) = packbf2(a2, b2);
        *reinterpret_cast<uint32_t*>(smem + SM_SPL + 2 * SPL_STRIDE + soff) = packbf2(a3, b3);
    }
    // |e_k|^2 all 512 codes (proven serial chain)
    {
        float* sc = reinterpret_cast<float*>(smem + SM_SC);
        #pragma unroll
        for (int kk = 0; kk < CB_K / THREADS; kk++) {
            int k = tid + kk * THREADS;
            const float* er = e_g + (size_t)k * EMB_D;
            float s = 0.f;
            #pragma unroll 16
            for (int d = 0; d < EMB_D; d++) s = __fmaf_rn(er[d], er[d], s);
            sc[k] = s;
        }
    }
    // A = |x|^2 per local row (1 row/thread, proven fma2 tree -> R8 bits)
    {
        const float4* xr = reinterpret_cast<const float4*>(x_g + (size_t)(ctabase + tid) * EMB_D);
        unsigned long long xx0[8];
        unsigned long long a0 = 0, a1 = 0, a2 = 0, a3 = 0;
        #pragma unroll
        for (int blk = 0; blk < 4; blk++) {
            #pragma unroll
            for (int i = 0; i < 4; i++) {
                float4 f = xr[blk * 4 + i];
                xx0[2 * i]     = pk2(f.x, f.y);
                xx0[2 * i + 1] = pk2(f.z, f.w);
            }
            a0 = fma2(xx0[0], xx0[0], a0); a1 = fma2(xx0[1], xx0[1], a1);
            a2 = fma2(xx0[2], xx0[2], a2); a3 = fma2(xx0[3], xx0[3], a3);
            a0 = fma2(xx0[4], xx0[4], a0); a1 = fma2(xx0[5], xx0[5], a1);
            a2 = fma2(xx0[6], xx0[6], a2); a3 = fma2(xx0[7], xx0[7], a3);
        }
        unsigned long long s = add2(add2(a0, a2), add2(a1, a3));
        reinterpret_cast<float*>(smem + SM_AS)[tid] = lo2(s) + hi2(s);
    }
    __syncthreads();

    const float* scp = reinterpret_cast<const float*>(smem + SM_SC);
    const float* As  = reinterpret_cast<const float*>(smem + SM_AS);

    // scalar-team state carried to the epilogue
    unsigned long long xa[32], xb[32];
    float best0 = 3.4e38f, best1 = 3.4e38f;
    int   bk0   = 0,       bk1   = 0;

    if (wid < 4) {
        // ============ SCALAR TEAM: exact R8 body, codes [0,344) ============
        const int row0 = ctabase + tid;          // local row tid
        const int row1 = row0 + 128;             // local row tid+128
        {
            const float4* xr0 = reinterpret_cast<const float4*>(x_g + (size_t)row0 * EMB_D);
            const float4* xr1 = reinterpret_cast<const float4*>(x_g + (size_t)row1 * EMB_D);
            #pragma unroll
            for (int i = 0; i < 16; i++) {
                float4 f = xr0[i];
                xa[2 * i]     = pk2(f.x, f.y);
                xa[2 * i + 1] = pk2(f.z, f.w);
                float4 g2 = xr1[i];
                xb[2 * i]     = pk2(g2.x, g2.y);
                xb[2 * i + 1] = pk2(g2.z, g2.w);
            }
        }
        const float A0 = As[tid];
        const float A1 = As[tid + 128];
        const ulonglong2* seu = reinterpret_cast<const ulonglong2*>(smem + SM_E);
        #pragma unroll 2
        for (int k = 0; k < S_CODES; k++) {
            const ulonglong2* ek = seu + k * 16;
            unsigned long long a0 = 0, a1 = 0, a2 = 0, a3 = 0;
            unsigned long long b0 = 0, b1 = 0, b2 = 0, b3 = 0;
            #pragma unroll
            for (int i = 0; i < 16; i += 2) {
                ulonglong2 e0 = ek[i];
                ulonglong2 e1 = ek[i + 1];
                a0 = fma2(xa[2 * i],     e0.x, a0);
                a1 = fma2(xa[2 * i + 1], e0.y, a1);
                a2 = fma2(xa[2 * i + 2], e1.x, a2);
                a3 = fma2(xa[2 * i + 3], e1.y, a3);
                b0 = fma2(xb[2 * i],     e0.x, b0);
                b1 = fma2(xb[2 * i + 1], e0.y, b1);
                b2 = fma2(xb[2 * i + 2], e1.x, b2);
                b3 = fma2(xb[2 * i + 3], e1.y, b3);
            }
            float ck = scp[k];
            unsigned long long s0 = add2(add2(a0, a2), add2(a1, a3));
            unsigned long long s1 = add2(add2(b0, b2), add2(b1, b3));
            float dot0 = lo2(s0) + hi2(s0);
            float dot1 = lo2(s1) + hi2(s1);
            float dd0 = __fadd_rn(__fmaf_rn(-2.0f, dot0, A0), ck);
            float dd1 = __fadd_rn(__fmaf_rn(-2.0f, dot1, A1), ck);
            if (dd0 < best0) { best0 = dd0; bk0 = k; }
            if (dd1 < best1) { best1 = dd1; bk1 = k; }
        }
    } else {
        // ============ TENSOR TEAM: R13/R15 6-product MMA, codes [344,512) ============
        const int tw = wid - 4;              // 0..3
        const int g  = lane >> 2;            // 0..7
        const int tq = lane & 3;             // 0..3
        const uint32_t swz = (uint32_t)(g << 2);
        float* bT = reinterpret_cast<float*>(smem + SM_BT);
        int*   iT = reinterpret_cast<int*>(smem + SM_IT);
        #pragma unroll 1
        for (int mt = 0; mt < 4; mt++) {
            const int mi = tw * 4 + mt;      // mtile 0..15 (16 rows each)
            const int wrow = ctabase + mi * 16;
            uint32_t areg[3][4][4];
            #pragma unroll
            for (int kt = 0; kt < 4; kt++)
                #pragma unroll
                for (int p = 0; p < 4; p++) {
                    int row = wrow + g + (p & 1) * 8;
                    int col = kt * 16 + 2 * tq + (p >> 1) * 8;
                    float2 v = *reinterpret_cast<const float2*>(x_g + (size_t)row * EMB_D + col);
                    __nv_bfloat16 u1, u2, u3, w1, w2, w3;
                    split3(v.x, u1, u2, u3);
                    split3(v.y, w1, w2, w3);
                    areg[0][kt][p] = packbf2(u1, w1);
                    areg[1][kt][p] = packbf2(u2, w2);
                    areg[2][kt][p] = packbf2(u3, w3);
                }
            float Arow0 = As[mi * 16 + g];
            float Arow1 = As[mi * 16 + g + 8];
            float tb0 = 3.4e38f, tb1 = 3.4e38f;
            int   ti0 = S_CODES, ti1 = S_CODES;
            #pragma unroll 1
            for (int ntl = 0; ntl < NT_T; ntl++) {
                const uint32_t roff = (uint32_t)((ntl * 8 + g) * 128);
                float cb[4] = {0.f, 0.f, 0.f, 0.f};
                float cs[4] = {0.f, 0.f, 0.f, 0.f};
                #pragma unroll
                for (int kt = 0; kt < 4; kt++) {
                    uint32_t w0 = (uint32_t)(kt * 8 + tq);
                    uint32_t d0 = (((w0    ) ^ swz) << 2);
                    uint32_t d1 = (((w0 + 4) ^ swz) << 2);
                    uint32_t e10 = *reinterpret_cast<const uint32_t*>(smem + SM_SPL + 0*SPL_STRIDE + roff + d0);
                    uint32_t e11 = *reinterpret_cast<const uint32_t*>(smem + SM_SPL + 0*SPL_STRIDE + roff + d1);
                    uint32_t e20 = *reinterpret_cast<const uint32_t*>(smem + SM_SPL + 1*SPL_STRIDE + roff + d0);
                    uint32_t e21 = *reinterpret_cast<const uint32_t*>(smem + SM_SPL + 1*SPL_STRIDE + roff + d1);
                    uint32_t e30 = *reinterpret_cast<const uint32_t*>(smem + SM_SPL + 2*SPL_STRIDE + roff + d0);
                    uint32_t e31 = *reinterpret_cast<const uint32_t*>(smem + SM_SPL + 2*SPL_STRIDE + roff + d1);
                    // exact R15 order: cb:x1e1 ; cs: x2e1, x1e2, x2e2, x3e1, x1e3
                    mma16816(cb, areg[0][kt], e10, e11);
                    mma16816(cs, areg[1][kt], e10, e11);
                    mma16816(cs, areg[0][kt], e20, e21);
                    mma16816(cs, areg[1][kt], e20, e21);
                    mma16816(cs, areg[2][kt], e10, e11);
                    mma16816(cs, areg[0][kt], e30, e31);
                }
                const int c0 = S_CODES + ntl * 8 + 2 * tq;
                const float ck0 = scp[c0], ck1 = scp[c0 + 1];
                float B00 = __fadd_rn(cb[0], cs[0]);
                float B01 = __fadd_rn(cb[1], cs[1]);
                float B10 = __fadd_rn(cb[2], cs[2]);
                float B11 = __fadd_rn(cb[3], cs[3]);
                float d00 = __fadd_rn(__fmaf_rn(-2.0f, B00, Arow0), ck0);
                float d01 = __fadd_rn(__fmaf_rn(-2.0f, B01, Arow0), ck1);
                float d10 = __fadd_rn(__fmaf_rn(-2.0f, B10, Arow1), ck0);
                float d11 = __fadd_rn(__fmaf_rn(-2.0f, B11, Arow1), ck1);
                if (d00 < tb0) { tb0 = d00; ti0 = c0; }
                if (d01 < tb0) { tb0 = d01; ti0 = c0 + 1; }
                if (d10 < tb1) { tb1 = d10; ti1 = c0; }
                if (d11 < tb1) { tb1 = d11; ti1 = c0 + 1; }
            }
            // tq-lane merge (min, lowest index on tie), write to smem
            {
                float b = tb0; int i = ti0;
                #pragma unroll
                for (int m = 1; m <= 2; m <<= 1) {
                    float ob = __shfl_xor_sync(0xffffffffu, b, m);
                    int   oi = __shfl_xor_sync(0xffffffffu, i, m);
                    if (ob < b || (ob == b && oi < i)) { b = ob; i = oi; }
                }
                if (tq == 0) { bT[mi * 16 + g] = b; iT[mi * 16 + g] = i; }
            }
            {
                float b = tb1; int i = ti1;
                #pragma unroll
                for (int m = 1; m <= 2; m <<= 1) {
                    float ob = __shfl_xor_sync(0xffffffffu, b, m);
                    int   oi = __shfl_xor_sync(0xffffffffu, i, m);
                    if (ob < b || (ob == b && oi < i)) { b = ob; i = oi; }
                }
                if (tq == 0) { bT[mi * 16 + g + 8] = b; iT[mi * 16 + g + 8] = i; }
            }
        }
    }
    __syncthreads();

    // ================= merge + epilogue (scalar threads own 2 rows) =================
    float sse = 0.f;
    if (wid < 4) {
        const float* bT = reinterpret_cast<const float*>(smem + SM_BT);
        const int*   iT = reinterpret_cast<const int*>(smem + SM_IT);
        // tensor codes are all higher-index: strict < keeps scalar on ties
        float tb = bT[tid];
        if (tb < best0) { best0 = tb; bk0 = iT[tid]; }
        tb = bT[tid + 128];
        if (tb < best1) { best1 = tb; bk1 = iT[tid + 128]; }

        const int row0 = ctabase + tid;
        const int row1 = row0 + 128;
        {
            const float* qr = e_g + (size_t)bk0 * EMB_D;
            float* orow = out + 1 + (size_t)row0 * EMB_D;
            float q[64];
            const float4* q4 = reinterpret_cast<const float4*>(qr);
            #pragma unroll
            for (int i = 0; i < 16; i++) {
                float4 qq = q4[i];
                q[4*i] = qq.x; q[4*i+1] = qq.y; q[4*i+2] = qq.z; q[4*i+3] = qq.w;
            }
            #pragma unroll
            for (int i = 0; i < 32; i++) {
                float d0 = q[2 * i]     - lo2(xa[i]);
                float d1 = q[2 * i + 1] - hi2(xa[i]);
                sse = __fmaf_rn(d0, d0, sse);
                sse = __fmaf_rn(d1, d1, sse);
            }
            orow[0] = q[0]; orow[1] = q[1]; orow[2] = q[2];
            float4* ov = reinterpret_cast<float4*>(orow + 3);
            #pragma unroll
            for (int i = 0; i < 15; i++) {
                float4 v;
                v.x = q[3+4*i]; v.y = q[4+4*i]; v.z = q[5+4*i]; v.w = q[6+4*i];
                ov[i] = v;
            }
            orow[63] = q[63];
            out[1 + Q_ELEMS + (size_t)row0] = (float)bk0;
        }
        {
            const float* qr = e_g + (size_t)bk1 * EMB_D;
            float* orow = out + 1 + (size_t)row1 * EMB_D;
            float q[64];
            const float4* q4 = reinterpret_cast<const float4*>(qr);
            #pragma unroll
            for (int i = 0; i < 16; i++) {
                float4 qq = q4[i];
                q[4*i] = qq.x; q[4*i+1] = qq.y; q[4*i+2] = qq.z; q[4*i+3] = qq.w;
            }
            #pragma unroll
            for (int i = 0; i < 32; i++) {
                float d0 = q[2 * i]     - lo2(xb[i]);
                float d1 = q[2 * i + 1] - hi2(xb[i]);
                sse = __fmaf_rn(d0, d0, sse);
                sse = __fmaf_rn(d1, d1, sse);
            }
            orow[0] = q[0]; orow[1] = q[1]; orow[2] = q[2];
            float4* ov = reinterpret_cast<float4*>(orow + 3);
            #pragma unroll
            for (int i = 0; i < 15; i++) {
                float4 v;
                v.x = q[3+4*i]; v.y = q[4+4*i]; v.z = q[5+4*i]; v.w = q[6+4*i];
                ov[i] = v;
            }
            orow[63] = q[63];
            out[1 + Q_ELEMS + (size_t)row1] = (float)bk1;
        }
    }

    // ================= CTA loss reduction (deterministic tree) =================
    float* sred = reinterpret_cast<float*>(smem + SM_RED);
    sred[tid] = sse;
    __syncthreads();
    #pragma unroll
    for (int off = THREADS / 2; off > 0; off >>= 1) {
        if (tid < off) sred[tid] = sred[tid] + sred[tid + off];
        __syncthreads();
    }
    if (tid == 0) g_partial[blockIdx.x] = sred[0];
}

// Final deterministic reduce: loss = 1.25 * SSE / (N*D)
__global__ void vq_reduce_kernel(float* __restrict__ out) {
    __shared__ double sd[GRID];
    int tid = threadIdx.x;
    sd[tid] = (double)g_partial[tid];
    __syncthreads();
    #pragma unroll
    for (int off = GRID / 2; off > 0; off >>= 1) {
        if (tid < off) sd[tid] = sd[tid] + sd[tid + off];
        __syncthreads();
    }
    if (tid == 0) {
        double mean = sd[0] / (double)((size_t)N_ROWS * EMB_D);
        out[0] = (float)(1.25 * mean);
    }
}

extern "C" void kernel_launch(void* const* d_in, const int* in_sizes, int n_in,
                              void* d_out, int out_size) {
    const float* x = (const float*)d_in[0];
    const float* e = (const float*)d_in[1];
    if (n_in >= 2 && in_sizes[0] == CB_K * EMB_D) {
        const float* t = x; x = e; e = t;
    }
    float* out = (float*)d_out;

    cudaFuncSetAttribute(vq_hybrid_kernel,
                         cudaFuncAttributeMaxDynamicSharedMemorySize, SM_TOTAL);
    vq_hybrid_kernel<<<GRID, THREADS, SM_TOTAL>>>(x, e, out);
    vq_reduce_kernel<<<1, GRID>>>(out);
}

// round 17
// speedup vs baseline: 1.5386x; 1.1596x over previous
#include <cuda_runtime.h>
#include <cuda_bf16.h>
#include <cstdint>

#define CB_K    512
#define S_CODES 320                      // scalar: codes [0,320)
#define T_CODES 192                      // tensor: codes [320,512)
#define NT_T    24                       // 192/8 n-tiles
#define EMB_D   64
#define N_ROWS  65536
#define CTA_ROWS 512
#define GRID    (N_ROWS / CTA_ROWS)      // 128 CTAs -> ONE wave
#define THREADS 384                      // warps 0-7 scalar, 8-11 tensor
#define Q_ELEMS ((size_t)N_ROWS * EMB_D)

#define SPL_STRIDE 24576                 // 192 codes x 128B per split
#define SM_E    0                        // fp32 codes[320][64] = 81920 B
#define SM_SPL  81920                    // 3 x 24576 = 73728 B
#define SM_SC   (SM_SPL + 3 * SPL_STRIDE)   // 155648: |e|^2 f32[512]
#define SM_AS   (SM_SC + 2048)           // 157696: A f32[512]
#define SM_BT   (SM_AS + 2048)           // 159744: tensor best f32[512]
#define SM_IT   (SM_BT + 2048)           // 161792: tensor idx i32[512]
#define SM_RED  (SM_IT + 2048)           // 163840: partials f32[512] (padded)
#define SM_TOTAL (SM_RED + 2048)         // 165888 B

__device__ float g_partial[GRID];

__device__ __forceinline__ void mma16816(float* c, const uint32_t* a,
                                         uint32_t b0, uint32_t b1) {
    asm volatile("mma.sync.aligned.m16n8k16.row.col.f32.bf16.bf16.f32 "
                 "{%0,%1,%2,%3}, {%4,%5,%6,%7}, {%8,%9}, {%0,%1,%2,%3};"
                 : "+f"(c[0]), "+f"(c[1]), "+f"(c[2]), "+f"(c[3])
                 : "r"(a[0]), "r"(a[1]), "r"(a[2]), "r"(a[3]), "r"(b0), "r"(b1));
}
__device__ __forceinline__ void split3(float v, __nv_bfloat16& s1,
                                       __nv_bfloat16& s2, __nv_bfloat16& s3) {
    s1 = __float2bfloat16_rn(v);
    float r = v - __bfloat162float(s1);
    s2 = __float2bfloat16_rn(r);
    s3 = __float2bfloat16_rn(r - __bfloat162float(s2));
}
__device__ __forceinline__ uint32_t packbf2(__nv_bfloat16 lo, __nv_bfloat16 hi) {
    return (uint32_t)__bfloat16_as_ushort(lo) | ((uint32_t)__bfloat16_as_ushort(hi) << 16);
}
// proven packed f32x2 helpers
__device__ __forceinline__ unsigned long long fma2(unsigned long long a,
                                                   unsigned long long b,
                                                   unsigned long long c) {
    unsigned long long r;
    asm("fma.rn.f32x2 %0, %1, %2, %3;" : "=l"(r) : "l"(a), "l"(b), "l"(c));
    return r;
}
__device__ __forceinline__ unsigned long long add2(unsigned long long a,
                                                   unsigned long long b) {
    unsigned long long r;
    asm("add.rn.f32x2 %0, %1, %2;" : "=l"(r) : "l"(a), "l"(b));
    return r;
}
__device__ __forceinline__ unsigned long long pk2(float lo, float hi) {
    unsigned long long r;
    asm("mov.b64 %0, {%1, %2};" : "=l"(r) : "f"(lo), "f"(hi));
    return r;
}
__device__ __forceinline__ float lo2(unsigned long long v) {
    return __uint_as_float((unsigned)(v & 0xffffffffull));
}
__device__ __forceinline__ float hi2(unsigned long long v) {
    return __uint_as_float((unsigned)(v >> 32));
}

__global__ void __launch_bounds__(THREADS, 1)
vq_hybrid_kernel(const float* __restrict__ x_g,
                 const float* __restrict__ e_g,
                 float* __restrict__ out) {
    extern __shared__ char smem[];
    const int tid  = threadIdx.x;
    const int lane = tid & 31;
    const int wid  = tid >> 5;
    const int ctabase = blockIdx.x * CTA_ROWS;

    // ================= staging (all 384 threads) =================
    {
        float4* dst = reinterpret_cast<float4*>(smem + SM_E);
        const float4* src = reinterpret_cast<const float4*>(e_g);
        for (int i = tid; i < S_CODES * 16; i += THREADS) dst[i] = src[i];
    }
    for (int i = tid; i < T_CODES * 32; i += THREADS) {
        int lc = i >> 5, w = i & 31;
        float2 v = reinterpret_cast<const float2*>(e_g)[(size_t)(S_CODES + lc) * 32 + w];
        __nv_bfloat16 a1, a2, a3, b1, b2, b3;
        split3(v.x, a1, a2, a3);
        split3(v.y, b1, b2, b3);
        uint32_t soff = (uint32_t)(lc * 128 + ((w ^ ((lc & 7) << 2)) << 2));
        *reinterpret_cast<uint32_t*>(smem + SM_SPL + 0 * SPL_STRIDE + soff) = packbf2(a1, b1);
        *reinterpret_cast<uint32_t*>(smem + SM_SPL + 1 * SPL_STRIDE + soff) = packbf2(a2, b2);
        *reinterpret_cast<uint32_t*>(smem + SM_SPL + 2 * SPL_STRIDE + soff) = packbf2(a3, b3);
    }
    // |e_k|^2 all 512 codes (proven serial chain)
    {
        float* sc = reinterpret_cast<float*>(smem + SM_SC);
        for (int k = tid; k < CB_K; k += THREADS) {
            const float* er = e_g + (size_t)k * EMB_D;
            float s = 0.f;
            #pragma unroll 16
            for (int d = 0; d < EMB_D; d++) s = __fmaf_rn(er[d], er[d], s);
            sc[k] = s;
        }
    }
    // A = |x|^2 per local row (proven fma2 tree -> R8 bits)
    for (int r = tid; r < CTA_ROWS; r += THREADS) {
        const float4* xr = reinterpret_cast<const float4*>(x_g + (size_t)(ctabase + r) * EMB_D);
        unsigned long long xx0[8];
        unsigned long long a0 = 0, a1 = 0, a2 = 0, a3 = 0;
        #pragma unroll
        for (int blk = 0; blk < 4; blk++) {
            #pragma unroll
            for (int i = 0; i < 4; i++) {
                float4 f = xr[blk * 4 + i];
                xx0[2 * i]     = pk2(f.x, f.y);
                xx0[2 * i + 1] = pk2(f.z, f.w);
            }
            a0 = fma2(xx0[0], xx0[0], a0); a1 = fma2(xx0[1], xx0[1], a1);
            a2 = fma2(xx0[2], xx0[2], a2); a3 = fma2(xx0[3], xx0[3], a3);
            a0 = fma2(xx0[4], xx0[4], a0); a1 = fma2(xx0[5], xx0[5], a1);
            a2 = fma2(xx0[6], xx0[6], a2); a3 = fma2(xx0[7], xx0[7], a3);
        }
        unsigned long long s = add2(add2(a0, a2), add2(a1, a3));
        reinterpret_cast<float*>(smem + SM_AS)[r] = lo2(s) + hi2(s);
    }
    __syncthreads();

    const float* scp = reinterpret_cast<const float*>(smem + SM_SC);
    const float* As  = reinterpret_cast<const float*>(smem + SM_AS);

    unsigned long long xa[32], xb[32];
    float best0 = 3.4e38f, best1 = 3.4e38f;
    int   bk0   = 0,       bk1   = 0;

    if (wid < 8) {
        // ========= SCALAR TEAM (256 thr, 2/SMSP): exact R8 body, codes [0,320) =========
        const int row0 = ctabase + tid;          // local rows tid, tid+256
        const int row1 = row0 + 256;
        {
            const float4* xr0 = reinterpret_cast<const float4*>(x_g + (size_t)row0 * EMB_D);
            const float4* xr1 = reinterpret_cast<const float4*>(x_g + (size_t)row1 * EMB_D);
            #pragma unroll
            for (int i = 0; i < 16; i++) {
                float4 f = xr0[i];
                xa[2 * i]     = pk2(f.x, f.y);
                xa[2 * i + 1] = pk2(f.z, f.w);
                float4 g2 = xr1[i];
                xb[2 * i]     = pk2(g2.x, g2.y);
                xb[2 * i + 1] = pk2(g2.z, g2.w);
            }
        }
        const float A0 = As[tid];
        const float A1 = As[tid + 256];
        const ulonglong2* seu = reinterpret_cast<const ulonglong2*>(smem + SM_E);
        #pragma unroll 2
        for (int k = 0; k < S_CODES; k++) {
            const ulonglong2* ek = seu + k * 16;
            unsigned long long a0 = 0, a1 = 0, a2 = 0, a3 = 0;
            unsigned long long b0 = 0, b1 = 0, b2 = 0, b3 = 0;
            #pragma unroll
            for (int i = 0; i < 16; i += 2) {
                ulonglong2 e0 = ek[i];
                ulonglong2 e1 = ek[i + 1];
                a0 = fma2(xa[2 * i],     e0.x, a0);
                a1 = fma2(xa[2 * i + 1], e0.y, a1);
                a2 = fma2(xa[2 * i + 2], e1.x, a2);
                a3 = fma2(xa[2 * i + 3], e1.y, a3);
                b0 = fma2(xb[2 * i],     e0.x, b0);
                b1 = fma2(xb[2 * i + 1], e0.y, b1);
                b2 = fma2(xb[2 * i + 2], e1.x, b2);
                b3 = fma2(xb[2 * i + 3], e1.y, b3);
            }
            float ck = scp[k];
            unsigned long long s0 = add2(add2(a0, a2), add2(a1, a3));
            unsigned long long s1 = add2(add2(b0, b2), add2(b1, b3));
            float dot0 = lo2(s0) + hi2(s0);
            float dot1 = lo2(s1) + hi2(s1);
            float dd0 = __fadd_rn(__fmaf_rn(-2.0f, dot0, A0), ck);
            float dd1 = __fadd_rn(__fmaf_rn(-2.0f, dot1, A1), ck);
            if (dd0 < best0) { best0 = dd0; bk0 = k; }
            if (dd1 < best1) { best1 = dd1; bk1 = k; }
        }
    } else {
        // ========= TENSOR TEAM (4 warps, 1/SMSP): R15 6-product MMA, codes [320,512) =========
        const int tw = wid - 8;              // 0..3
        const int g  = lane >> 2;
        const int tq = lane & 3;
        const uint32_t swz = (uint32_t)(g << 2);
        float* bT = reinterpret_cast<float*>(smem + SM_BT);
        int*   iT = reinterpret_cast<int*>(smem + SM_IT);
        #pragma unroll 1
        for (int mt = 0; mt < 8; mt++) {
            const int mi = tw * 8 + mt;      // mtile 0..31 (16 rows each)
            const int wrow = ctabase + mi * 16;
            uint32_t areg[3][4][4];
            #pragma unroll
            for (int kt = 0; kt < 4; kt++)
                #pragma unroll
                for (int p = 0; p < 4; p++) {
                    int row = wrow + g + (p & 1) * 8;
                    int col = kt * 16 + 2 * tq + (p >> 1) * 8;
                    float2 v = *reinterpret_cast<const float2*>(x_g + (size_t)row * EMB_D + col);
                    __nv_bfloat16 u1, u2, u3, w1, w2, w3;
                    split3(v.x, u1, u2, u3);
                    split3(v.y, w1, w2, w3);
                    areg[0][kt][p] = packbf2(u1, w1);
                    areg[1][kt][p] = packbf2(u2, w2);
                    areg[2][kt][p] = packbf2(u3, w3);
                }
            float Arow0 = As[mi * 16 + g];
            float Arow1 = As[mi * 16 + g + 8];
            float tb0 = 3.4e38f, tb1 = 3.4e38f;
            int   ti0 = S_CODES, ti1 = S_CODES;
            #pragma unroll 1
            for (int ntl = 0; ntl < NT_T; ntl++) {
                const uint32_t roff = (uint32_t)((ntl * 8 + g) * 128);
                float cb[4] = {0.f, 0.f, 0.f, 0.f};
                float cs[4] = {0.f, 0.f, 0.f, 0.f};
                #pragma unroll
                for (int kt = 0; kt < 4; kt++) {
                    uint32_t w0 = (uint32_t)(kt * 8 + tq);
                    uint32_t d0 = (((w0    ) ^ swz) << 2);
                    uint32_t d1 = (((w0 + 4) ^ swz) << 2);
                    uint32_t e10 = *reinterpret_cast<const uint32_t*>(smem + SM_SPL + 0*SPL_STRIDE + roff + d0);
                    uint32_t e11 = *reinterpret_cast<const uint32_t*>(smem + SM_SPL + 0*SPL_STRIDE + roff + d1);
                    uint32_t e20 = *reinterpret_cast<const uint32_t*>(smem + SM_SPL + 1*SPL_STRIDE + roff + d0);
                    uint32_t e21 = *reinterpret_cast<const uint32_t*>(smem + SM_SPL + 1*SPL_STRIDE + roff + d1);
                    uint32_t e30 = *reinterpret_cast<const uint32_t*>(smem + SM_SPL + 2*SPL_STRIDE + roff + d0);
                    uint32_t e31 = *reinterpret_cast<const uint32_t*>(smem + SM_SPL + 2*SPL_STRIDE + roff + d1);
                    mma16816(cb, areg[0][kt], e10, e11);
                    mma16816(cs, areg[1][kt], e10, e11);
                    mma16816(cs, areg[0][kt], e20, e21);
                    mma16816(cs, areg[1][kt], e20, e21);
                    mma16816(cs, areg[2][kt], e10, e11);
                    mma16816(cs, areg[0][kt], e30, e31);
                }
                const int c0 = S_CODES + ntl * 8 + 2 * tq;
                const float ck0 = scp[c0], ck1 = scp[c0 + 1];
                float B00 = __fadd_rn(cb[0], cs[0]);
                float B01 = __fadd_rn(cb[1], cs[1]);
                float B10 = __fadd_rn(cb[2], cs[2]);
                float B11 = __fadd_rn(cb[3], cs[3]);
                float d00 = __fadd_rn(__fmaf_rn(-2.0f, B00, Arow0), ck0);
                float d01 = __fadd_rn(__fmaf_rn(-2.0f, B01, Arow0), ck1);
                float d10 = __fadd_rn(__fmaf_rn(-2.0f, B10, Arow1), ck0);
                float d11 = __fadd_rn(__fmaf_rn(-2.0f, B11, Arow1), ck1);
                if (d00 < tb0) { tb0 = d00; ti0 = c0; }
                if (d01 < tb0) { tb0 = d01; ti0 = c0 + 1; }
                if (d10 < tb1) { tb1 = d10; ti1 = c0; }
                if (d11 < tb1) { tb1 = d11; ti1 = c0 + 1; }
            }
            {
                float b = tb0; int i = ti0;
                #pragma unroll
                for (int m = 1; m <= 2; m <<= 1) {
                    float ob = __shfl_xor_sync(0xffffffffu, b, m);
                    int   oi = __shfl_xor_sync(0xffffffffu, i, m);
                    if (ob < b || (ob == b && oi < i)) { b = ob; i = oi; }
                }
                if (tq == 0) { bT[mi * 16 + g] = b; iT[mi * 16 + g] = i; }
            }
            {
                float b = tb1; int i = ti1;
                #pragma unroll
                for (int m = 1; m <= 2; m <<= 1) {
                    float ob = __shfl_xor_sync(0xffffffffu, b, m);
                    int   oi = __shfl_xor_sync(0xffffffffu, i, m);
                    if (ob < b || (ob == b && oi < i)) { b = ob; i = oi; }
                }
                if (tq == 0) { bT[mi * 16 + g + 8] = b; iT[mi * 16 + g + 8] = i; }
            }
        }
    }
    __syncthreads();

    // ================= merge + epilogue (scalar threads own 2 rows) =================
    float sse = 0.f;
    if (wid < 8) {
        const float* bT = reinterpret_cast<const float*>(smem + SM_BT);
        const int*   iT = reinterpret_cast<const int*>(smem + SM_IT);
        float tb = bT[tid];
        if (tb < best0) { best0 = tb; bk0 = iT[tid]; }   // tensor idx higher: < keeps scalar on tie
        tb = bT[tid + 256];
        if (tb < best1) { best1 = tb; bk1 = iT[tid + 256]; }

        const int row0 = ctabase + tid;
        const int row1 = row0 + 256;
        {
            const float4* q4 = reinterpret_cast<const float4*>(e_g + (size_t)bk0 * EMB_D);
            float* orow = out + 1 + (size_t)row0 * EMB_D;
            float q[64];
            #pragma unroll
            for (int i = 0; i < 16; i++) {
                float4 qq = q4[i];
                q[4*i] = qq.x; q[4*i+1] = qq.y; q[4*i+2] = qq.z; q[4*i+3] = qq.w;
            }
            #pragma unroll
            for (int i = 0; i < 32; i++) {
                float d0 = q[2 * i]     - lo2(xa[i]);
                float d1 = q[2 * i + 1] - hi2(xa[i]);
                sse = __fmaf_rn(d0, d0, sse);
                sse = __fmaf_rn(d1, d1, sse);
            }
            orow[0] = q[0]; orow[1] = q[1]; orow[2] = q[2];
            float4* ov = reinterpret_cast<float4*>(orow + 3);
            #pragma unroll
            for (int i = 0; i < 15; i++) {
                float4 v;
                v.x = q[3+4*i]; v.y = q[4+4*i]; v.z = q[5+4*i]; v.w = q[6+4*i];
                ov[i] = v;
            }
            orow[63] = q[63];
            out[1 + Q_ELEMS + (size_t)row0] = (float)bk0;
        }
        {
            const float4* q4 = reinterpret_cast<const float4*>(e_g + (size_t)bk1 * EMB_D);
            float* orow = out + 1 + (size_t)row1 * EMB_D;
            float q[64];
            #pragma unroll
            for (int i = 0; i < 16; i++) {
                float4 qq = q4[i];
                q[4*i] = qq.x; q[4*i+1] = qq.y; q[4*i+2] = qq.z; q[4*i+3] = qq.w;
            }
            #pragma unroll
            for (int i = 0; i < 32; i++) {
                float d0 = q[2 * i]     - lo2(xb[i]);
                float d1 = q[2 * i + 1] - hi2(xb[i]);
                sse = __fmaf_rn(d0, d0, sse);
                sse = __fmaf_rn(d1, d1, sse);
            }
            orow[0] = q[0]; orow[1] = q[1]; orow[2] = q[2];
            float4* ov = reinterpret_cast<float4*>(orow + 3);
            #pragma unroll
            for (int i = 0; i < 15; i++) {
                float4 v;
                v.x = q[3+4*i]; v.y = q[4+4*i]; v.z = q[5+4*i]; v.w = q[6+4*i];
                ov[i] = v;
            }
            orow[63] = q[63];
            out[1 + Q_ELEMS + (size_t)row1] = (float)bk1;
        }
    }

    // ========== CTA loss reduction (padded to 512, deterministic tree) ==========
    float* sred = reinterpret_cast<float*>(smem + SM_RED);
    sred[tid] = sse;
    if (tid < 128) sred[THREADS + tid] = 0.f;   // pad 384 -> 512
    __syncthreads();
    #pragma unroll
    for (int off = 256; off > 0; off >>= 1) {
        if (tid < off && tid + off < 512) sred[tid] = sred[tid] + sred[tid + off];
        __syncthreads();
    }
    if (tid == 0) g_partial[blockIdx.x] = sred[0];
}

// Final deterministic reduce over 128 partials: loss = 1.25 * SSE / (N*D)
__global__ void vq_reduce_kernel(float* __restrict__ out) {
    __shared__ double sd[GRID];
    int tid = threadIdx.x;
    sd[tid] = (double)g_partial[tid];
    __syncthreads();
    #pragma unroll
    for (int off = GRID / 2; off > 0; off >>= 1) {
        if (tid < off) sd[tid] = sd[tid] + sd[tid + off];
        __syncthreads();
    }
    if (tid == 0) {
        double mean = sd[0] / (double)((size_t)N_ROWS * EMB_D);
        out[0] = (float)(1.25 * mean);
    }
}

extern "C" void kernel_launch(void* const* d_in, const int* in_sizes, int n_in,
                              void* d_out, int out_size) {
    const float* x = (const float*)d_in[0];
    const float* e = (const float*)d_in[1];
    if (n_in >= 2 && in_sizes[0] == CB_K * EMB_D) {
        const float* t = x; x = e; e = t;
    }
    float* out = (float*)d_out;

    cudaFuncSetAttribute(vq_hybrid_kernel,
                         cudaFuncAttributeMaxDynamicSharedMemorySize, SM_TOTAL);
    vq_hybrid_kernel<<<GRID, THREADS, SM_TOTAL>>>(x, e, out);
    vq_reduce_kernel<<<1, GRID>>>(out);
}